// round 4
// baseline (speedup 1.0000x reference)
#include <cuda_runtime.h>
#include <cstdint>

#define B_     512
#define T_     2048
#define D_     64
#define H_     66
#define G4     264            // 4*H
#define BPB    4              // batches per block
#define NBLK   (B_ / BPB)     // 128 blocks -> one wave
#define NTHR   576
#define GATE_T 288

__device__ float    g_hT[B_ * H_];
__device__ unsigned g_done = 0;

// ---- packed f32x2 helpers ----
#define FMA2(d,a,b,c)   asm("fma.rn.f32x2 %0, %1, %2, %3;" : "=l"(d) : "l"(a), "l"(b), "l"(c))
#define ADD2(d,a,b)     asm("add.rn.f32x2 %0, %1, %2;"     : "=l"(d) : "l"(a), "l"(b))
#define PACK2(d,lo,hi)  asm("mov.b64 %0, {%1, %2};"        : "=l"(d) : "f"(lo), "f"(hi))
#define UNPACK2(lo,hi,s) asm("mov.b64 {%0, %1}, %2;"       : "=f"(lo), "=f"(hi) : "l"(s))

__device__ __forceinline__ float sigm_(float x) {
    return __fdividef(1.f, 1.f + __expf(-x));
}

__global__ __launch_bounds__(NTHR, 1) void fused_lstm_ws(
    const float* __restrict__ x,     const float* __restrict__ W_ih,
    const float* __restrict__ W_hh,  const float* __restrict__ b_ih,
    const float* __restrict__ b_hh,  const float* __restrict__ gamma,
    const float* __restrict__ beta,  const float* __restrict__ fc_w,
    const float* __restrict__ fc_b,  float* __restrict__ out)
{
    // sh_h: 4 rows of 68 floats (66 + zero pad) + 4-float tail pad so the
    // zero-weighted 18th chunk of half=1 stays in-bounds.
    __shared__ __align__(16) float sh_h[BPB * 68 + 4];
    __shared__ __align__(16) float sh_x[2][BPB][D_];     // double-buffered x rows
    __shared__ __align__(16) float sh_xp[2][BPB][G4];    // double-buffered x-projection
    __shared__ __align__(16) float sh_g[BPB][G4];        // activated gates
    __shared__ float s_a[H_], s_b[H_];
    __shared__ unsigned s_last;

    const int tid = threadIdx.x;
    const int b0  = blockIdx.x * BPB;
    const bool is_gate = (tid < GATE_T);

    // role id, clamped so pad lanes (264..287 of each group) duplicate id 263:
    // keeps every warp convergent through the shuffles.
    const int rid = is_gate ? tid : (tid - GATE_T);
    const int j   = (rid < G4) ? rid : (G4 - 1);
    const int r2   = j >> 1;        // 0..131  (rows r2 and r2+132)
    const int half = j & 1;         // k-split half; partner = lane^1
    const int ob   = 2 * half;      // own batches {ob, ob+1}
    const int fb   = 2 - 2 * half;  // foreign batches {fb, fb+1}

    // ---- unified weight registers (one live range for both roles) ----
    // gate: 2 rows of W_hh, half-k (9 chunks of 4 floats, zero-padded)
    // proj: 2 rows of W_ih, half-k (8 chunks)
    unsigned long long wA[18], wB[18];
    float biasA = 0.f, biasB = 0.f;
    if (is_gate) {
        const float* wa = W_hh + (size_t)r2 * H_;
        const float* wb = W_hh + (size_t)(r2 + 132) * H_;
        #pragma unroll
        for (int kk = 0; kk < 9; kk++) {
            #pragma unroll
            for (int s = 0; s < 2; s++) {
                const int f = 2 * (2 * (9 * half + kk) + s);
                const float alo = (f     < H_) ? wa[f]     : 0.f;
                const float ahi = (f + 1 < H_) ? wa[f + 1] : 0.f;
                const float blo = (f     < H_) ? wb[f]     : 0.f;
                const float bhi = (f + 1 < H_) ? wb[f + 1] : 0.f;
                PACK2(wA[2 * kk + s], alo, ahi);
                PACK2(wB[2 * kk + s], blo, bhi);
            }
        }
    } else {
        const ulonglong2* wa = ((const ulonglong2*)(W_ih + (size_t)r2 * D_)) + 8 * half;
        const ulonglong2* wb = ((const ulonglong2*)(W_ih + (size_t)(r2 + 132) * D_)) + 8 * half;
        #pragma unroll
        for (int kk = 0; kk < 8; kk++) {
            ulonglong2 va = wa[kk]; wA[2*kk] = va.x; wA[2*kk+1] = va.y;
            ulonglong2 vb = wb[kk]; wB[2*kk] = vb.x; wB[2*kk+1] = vb.y;
        }
        biasA = b_ih[r2] + b_hh[r2];
        biasB = b_ih[r2 + 132] + b_hh[r2 + 132];
    }

    // ---- init: zero h (+pads), stage x(0)->sh_x[0], x(1)->sh_x[1] ----
    for (int i = tid; i < BPB * 68 + 4; i += NTHR) sh_h[i] = 0.f;
    if (tid < 2 * BPB * (D_ / 4)) {                  // 128 threads, one float4 each
        const int buf = tid >> 6, idx = tid & 63, q = idx >> 4, e = idx & 15;
        ((float4*)sh_x[buf][q])[e] =
            ((const float4*)(x + ((size_t)(b0 + q) * T_ + buf) * D_))[e];
    }
    __syncthreads();

    // proj step: half-dot over xin rows, shuffle-combine, store 4 outputs
    auto proj_step = [&](const float (*xin)[D_], float (*xpout)[G4]) {
        float pAl[BPB], pBl[BPB];
        #pragma unroll
        for (int q = 0; q < BPB; q++) {
            const ulonglong2* hp = ((const ulonglong2*)xin[q]) + 8 * half;
            unsigned long long a0 = 0ull, a1 = 0ull, c0 = 0ull, c1 = 0ull;
            #pragma unroll
            for (int kk = 0; kk < 8; kk++) {
                ulonglong2 v = hp[kk];
                FMA2(a0, wA[2*kk],   v.x, a0); FMA2(a1, wA[2*kk+1], v.y, a1);
                FMA2(c0, wB[2*kk],   v.x, c0); FMA2(c1, wB[2*kk+1], v.y, c1);
            }
            ADD2(a0, a0, a1); ADD2(c0, c0, c1);
            float lo, hi;
            UNPACK2(lo, hi, a0); pAl[q] = lo + hi;
            UNPACK2(lo, hi, c0); pBl[q] = lo + hi;
        }
        const float rA0 = __shfl_xor_sync(0xffffffffu, pAl[fb],     1);
        const float rA1 = __shfl_xor_sync(0xffffffffu, pAl[fb + 1], 1);
        const float rB0 = __shfl_xor_sync(0xffffffffu, pBl[fb],     1);
        const float rB1 = __shfl_xor_sync(0xffffffffu, pBl[fb + 1], 1);
        if (rid < G4) {
            xpout[ob    ][r2      ] = pAl[ob]     + rA0 + biasA;
            xpout[ob + 1][r2      ] = pAl[ob + 1] + rA1 + biasA;
            xpout[ob    ][r2 + 132] = pBl[ob]     + rB0 + biasB;
            xpout[ob + 1][r2 + 132] = pBl[ob + 1] + rB1 + biasB;
        }
    };

    // prologue: xp(0) -> sh_xp[0]
    if (!is_gate) proj_step(sh_x[0], sh_xp[0]);
    __syncthreads();

    float c_ = 0.f, h_ = 0.f;
    const int q0 = (tid < G4) ? tid / H_ : 0;    // cell-update mapping
    const int r  = (tid < G4) ? tid % H_ : 0;

    for (int t = 0; t < T_; t++) {
        const int pc = t & 1, pn = pc ^ 1;
        if (is_gate) {
            // ---- half-dot over h for all 4 batches, 2 rows ----
            float pAl[BPB], pBl[BPB];
            #pragma unroll
            for (int q = 0; q < BPB; q++) {
                const ulonglong2* hp = ((const ulonglong2*)(sh_h + q * 68)) + 9 * half;
                unsigned long long a0 = 0ull, a1 = 0ull, c0 = 0ull, c1 = 0ull;
                #pragma unroll
                for (int kk = 0; kk < 9; kk++) {
                    ulonglong2 v = hp[kk];
                    FMA2(a0, wA[2*kk],   v.x, a0); FMA2(a1, wA[2*kk+1], v.y, a1);
                    FMA2(c0, wB[2*kk],   v.x, c0); FMA2(c1, wB[2*kk+1], v.y, c1);
                }
                ADD2(a0, a0, a1); ADD2(c0, c0, c1);
                float lo, hi;
                UNPACK2(lo, hi, a0); pAl[q] = lo + hi;
                UNPACK2(lo, hi, c0); pBl[q] = lo + hi;
            }
            // exchange foreign-batch partials with lane partner
            const float rA0 = __shfl_xor_sync(0xffffffffu, pAl[fb],     1);
            const float rA1 = __shfl_xor_sync(0xffffffffu, pAl[fb + 1], 1);
            const float rB0 = __shfl_xor_sync(0xffffffffu, pBl[fb],     1);
            const float rB1 = __shfl_xor_sync(0xffffffffu, pBl[fb + 1], 1);

            const float preA0 = pAl[ob]     + rA0 + sh_xp[pc][ob    ][r2];
            const float preA1 = pAl[ob + 1] + rA1 + sh_xp[pc][ob + 1][r2];
            const float preB0 = pBl[ob]     + rB0 + sh_xp[pc][ob    ][r2 + 132];
            const float preB1 = pBl[ob + 1] + rB1 + sh_xp[pc][ob + 1][r2 + 132];

            const float gA0 = sigm_(preA0);           // rows [0,132): i/f -> sigmoid
            const float gA1 = sigm_(preA1);
            float gB0, gB1;                           // rows [132,264): g (tanh) | o (sigmoid)
            if (r2 < H_) {
                gB0 = 2.f * sigm_(2.f * preB0) - 1.f;
                gB1 = 2.f * sigm_(2.f * preB1) - 1.f;
            } else {
                gB0 = sigm_(preB0);
                gB1 = sigm_(preB1);
            }
            if (rid < G4) {
                sh_g[ob    ][r2      ] = gA0;
                sh_g[ob + 1][r2      ] = gA1;
                sh_g[ob    ][r2 + 132] = gB0;
                sh_g[ob + 1][r2 + 132] = gB1;
            }
            asm volatile("bar.sync 1, 288;" ::: "memory");   // gate-group barrier
            if (tid < G4) {                                  // (q0, r) cell update
                const float i_ = sh_g[q0][r];
                const float f_ = sh_g[q0][H_ + r];
                const float gg = sh_g[q0][2 * H_ + r];
                const float o_ = sh_g[q0][3 * H_ + r];
                c_ = f_ * c_ + i_ * gg;
                const float th = 2.f * sigm_(2.f * c_) - 1.f;
                h_ = o_ * th;
                sh_h[q0 * 68 + r] = h_;
            }
        } else {
            // ---- proj group: prefetch x(t+2) early, compute xp(t+1) ----
            float4 pre4;
            const bool do_pre = (rid < BPB * (D_ / 4)) && (t + 2 < T_);
            const int qq = rid >> 4, e = rid & 15;
            if (do_pre)
                pre4 = ((const float4*)(x + ((size_t)(b0 + qq) * T_ + (t + 2)) * D_))[e];
            if (t + 1 < T_)
                proj_step(sh_x[pn], sh_xp[pn]);
            if (do_pre)
                ((float4*)sh_x[pc][qq])[e] = pre4;   // into retired buffer
        }
        __syncthreads();   // publishes h(t), xp(t+1), x(t+2)
    }

    // ---- publish h_T; elect last block ----
    if (is_gate && tid < G4)
        g_hT[(b0 + q0) * H_ + r] = h_;
    __threadfence();
    __syncthreads();
    if (tid == 0) {
        unsigned old = atomicAdd(&g_done, 1);
        s_last = (old == NBLK - 1) ? 1u : 0u;
    }
    __syncthreads();
    if (!s_last) return;
    if (tid == 0) g_done = 0;            // reset for deterministic graph replay
    __threadfence();

    // ---- BN stats (last block) ----
    if (tid < G4) {
        float s = 0.f, qs = 0.f;
        for (int b = q0 * (B_ / BPB); b < (q0 + 1) * (B_ / BPB); b++) {
            const float v = g_hT[b * H_ + r];
            s += v; qs += v * v;
        }
        sh_g[q0][r] = s;
        sh_h[q0 * 68 + r] = qs;
    }
    __syncthreads();
    if (tid < H_) {
        const float S = sh_g[0][tid] + sh_g[1][tid] + sh_g[2][tid] + sh_g[3][tid];
        const float Q = sh_h[0*68 + tid] + sh_h[1*68 + tid] + sh_h[2*68 + tid] + sh_h[3*68 + tid];
        const float mean = S * (1.f / B_);
        const float var  = Q * (1.f / B_) - mean * mean;
        const float a    = gamma[tid] * rsqrtf(var + 1e-5f);
        s_a[tid] = a * fc_w[tid];
        s_b[tid] = (beta[tid] - mean * a) * fc_w[tid];
    }
    __syncthreads();

    // ---- head ----
    const float f0 = fc_b[0];
    for (int b = tid; b < B_; b += NTHR) {
        float acc = f0;
        #pragma unroll
        for (int jj = 0; jj < H_; jj++)
            acc += s_a[jj] * g_hT[b * H_ + jj] + s_b[jj];
        out[b] = acc;
    }
}

extern "C" void kernel_launch(void* const* d_in, const int* in_sizes, int n_in,
                              void* d_out, int out_size)
{
    const float* x     = (const float*)d_in[0];
    const float* W_ih  = (const float*)d_in[1];
    const float* W_hh  = (const float*)d_in[2];
    const float* b_ih  = (const float*)d_in[3];
    const float* b_hh  = (const float*)d_in[4];
    const float* gamma = (const float*)d_in[5];
    const float* beta  = (const float*)d_in[6];
    const float* fc_w  = (const float*)d_in[7];
    const float* fc_b  = (const float*)d_in[8];
    float* out = (float*)d_out;

    fused_lstm_ws<<<NBLK, NTHR>>>(x, W_ih, W_hh, b_ih, b_hh,
                                  gamma, beta, fc_w, fc_b, out);
}

// round 6
// speedup vs baseline: 1.3242x; 1.3242x over previous
#include <cuda_runtime.h>
#include <cstdint>

#define B_     512
#define T_     2048
#define D_     64
#define H_     66
#define G4     264            // 4*H
#define BPB    4              // batches per block
#define NBLK   (B_ / BPB)     // 128 blocks -> one wave
#define NTHR   576
#define GATE_T 288

__device__ float    g_hT[B_ * H_];
__device__ unsigned g_done = 0;

// ---- packed f32x2 helpers (sm_103a FFMA2 path) ----
#define FMA2(d,a,b,c)   asm("fma.rn.f32x2 %0, %1, %2, %3;" : "=l"(d) : "l"(a), "l"(b), "l"(c))
#define ADD2(d,a,b)     asm("add.rn.f32x2 %0, %1, %2;"     : "=l"(d) : "l"(a), "l"(b))
#define PACK2(d,lo,hi)  asm("mov.b64 %0, {%1, %2};"        : "=l"(d) : "f"(lo), "f"(hi))
#define UNPACK2(lo,hi,s) asm("mov.b64 {%0, %1}, %2;"       : "=f"(lo), "=f"(hi) : "l"(s))

// named barriers:
//   1,2 = gate-internal (288)        7 = proj-internal (288)
//   3/4 = RDY0/RDY1  (proj arrives, gate syncs; 576)
//   5/6 = FRE0/FRE1  (gate arrives, proj syncs; 576)
#define BSYNC(id, n)   asm volatile("bar.sync %0, %1;"   :: "n"(id), "n"(n) : "memory")
#define BARR(id, n)    asm volatile("bar.arrive %0, %1;" :: "n"(id), "n"(n) : "memory")
#define BSYNCR(id, n)  asm volatile("bar.sync %0, %1;"   :: "r"(id), "n"(n) : "memory")
#define BARRR(id, n)   asm volatile("bar.arrive %0, %1;" :: "r"(id), "n"(n) : "memory")

__device__ __forceinline__ float sigm_(float x) {
    return __fdividef(1.f, 1.f + __expf(-x));
}

__global__ __launch_bounds__(NTHR, 1) void fused_lstm_ws(
    const float* __restrict__ x,     const float* __restrict__ W_ih,
    const float* __restrict__ W_hh,  const float* __restrict__ b_ih,
    const float* __restrict__ b_hh,  const float* __restrict__ gamma,
    const float* __restrict__ beta,  const float* __restrict__ fc_w,
    const float* __restrict__ fc_b,  float* __restrict__ out)
{
    __shared__ __align__(16) float sh_h[BPB * 68 + 4];   // h rows (66 + pads)
    __shared__ __align__(16) float sh_x[2][BPB][D_];     // double-buffered x rows
    __shared__ __align__(16) float sh_xp[2][BPB][G4];    // double-buffered x-projection
    __shared__ __align__(16) float sh_g[BPB][G4];        // activated gates
    __shared__ float s_a[H_], s_b[H_];
    __shared__ unsigned s_last;

    const int tid = threadIdx.x;
    const int b0  = blockIdx.x * BPB;
    const bool is_gate = (tid < GATE_T);
    const int rid = is_gate ? tid : (tid - GATE_T);   // role id; active < 264

    // ---- unified weight registers (single live range for both roles) ----
    unsigned long long w[34];
    float bias = 0.f;
    if (is_gate) {
        if (rid < G4) {
            const float* wr = W_hh + (size_t)rid * H_;
            #pragma unroll
            for (int i = 0; i < 33; i++) PACK2(w[i], wr[2*i], wr[2*i + 1]);
            PACK2(w[33], 0.f, 0.f);     // zero pad covers sh_h[66..67]
        }
    } else {
        if (rid < G4) {
            const ulonglong2* wp = (const ulonglong2*)(W_ih + (size_t)rid * D_);
            #pragma unroll
            for (int i = 0; i < 16; i++) { ulonglong2 v = wp[i]; w[2*i] = v.x; w[2*i+1] = v.y; }
            bias = b_ih[rid] + b_hh[rid];
        }
    }

    // ---- init: zero h (+pads), stage x(0)->buf0, x(1)->buf1 ----
    for (int i = tid; i < BPB * 68 + 4; i += NTHR) sh_h[i] = 0.f;
    if (tid < 2 * BPB * (D_ / 4)) {                  // 128 threads, one float4 each
        const int buf = tid >> 6, idx = tid & 63, q = idx >> 4, e = idx & 15;
        ((float4*)sh_x[buf][q])[e] =
            ((const float4*)(x + ((size_t)(b0 + q) * T_ + buf) * D_))[e];
    }
    __syncthreads();

    // proj step: full-k dot per batch, weights in regs, x broadcast from smem
    auto proj_step = [&](const float (*xin)[D_], float (*xpout)[G4]) {
        #pragma unroll
        for (int q = 0; q < BPB; q++) {
            const ulonglong2* hp = (const ulonglong2*)xin[q];
            unsigned long long a0, a1 = 0ull;
            PACK2(a0, bias, 0.f);
            #pragma unroll
            for (int k = 0; k < 16; k++) {
                ulonglong2 v = hp[k];
                FMA2(a0, w[2*k],     v.x, a0);
                FMA2(a1, w[2*k + 1], v.y, a1);
            }
            ADD2(a0, a0, a1);
            float lo, hi; UNPACK2(lo, hi, a0);
            if (rid < G4) xpout[q][rid] = lo + hi;
        }
    };

    // ---- prologue ----
    // proj: xp(0) -> buffer 0, then arrive RDY0 (its ONLY prime).
    // gate: arrive FRE1 once (buffer 1 starts free; gate never syncs FRE*).
    if (!is_gate) {
        proj_step(sh_x[0], sh_xp[0]);
        __threadfence_block();
        BARR(3, NTHR);               // RDY0: xp(0) ready
    } else {
        BARR(6, NTHR);               // FRE1: buffer 1 free
    }

    float c_ = 0.f, h_ = 0.f;
    const int q0 = (tid < G4) ? tid / H_ : 0;    // cell-update mapping
    const int r  = (tid < G4) ? tid % H_ : 0;
    const bool tg = is_gate && (rid >= 2 * H_) && (rid < 3 * H_);   // tanh gate?

    for (int t = 0; t < T_; t++) {
        const int pc = t & 1, pn = pc ^ 1;
        if (is_gate) {
            BSYNCR(3 + pc, NTHR);                    // wait: xp(t) ready in buffer pc
            // hoist xp reads
            const int jj = (rid < G4) ? rid : (G4 - 1);
            float xpv[BPB];
            #pragma unroll
            for (int q = 0; q < BPB; q++) xpv[q] = sh_xp[pc][q][jj];

            // dot(W_hh[rid,:], h_q) for 4 batches
            float pre[BPB];
            #pragma unroll
            for (int q = 0; q < BPB; q++) {
                const ulonglong2* hp = (const ulonglong2*)(sh_h + q * 68);
                unsigned long long a0 = 0ull, a1 = 0ull;
                #pragma unroll
                for (int k = 0; k < 17; k++) {
                    ulonglong2 v = hp[k];
                    FMA2(a0, w[2*k],     v.x, a0);
                    FMA2(a1, w[2*k + 1], v.y, a1);
                }
                ADD2(a0, a0, a1);
                float lo, hi; UNPACK2(lo, hi, a0);
                pre[q] = lo + hi + xpv[q];
            }
            BARRR(5 + pc, NTHR);                     // FRE[pc]: xp(t) consumed

            if (rid < G4) {                          // activations
                #pragma unroll
                for (int q = 0; q < BPB; q++) {
                    const float s = tg ? (2.f * sigm_(2.f * pre[q]) - 1.f) : sigm_(pre[q]);
                    sh_g[q][rid] = s;
                }
            }
            BSYNC(1, GATE_T);                        // gates published (gate-internal)
            if (tid < G4) {                          // (q0, r) cell update
                const float i_ = sh_g[q0][r];
                const float f_ = sh_g[q0][H_ + r];
                const float gg = sh_g[q0][2 * H_ + r];
                const float o_ = sh_g[q0][3 * H_ + r];
                c_ = f_ * c_ + i_ * gg;
                const float th = 2.f * sigm_(2.f * c_) - 1.f;
                h_ = o_ * th;
                sh_h[q0 * 68 + r] = h_;
            }
            BSYNC(2, GATE_T);                        // h(t) published (gate-internal)
        } else {
            // ---- proj group: prefetch x(t+2), compute xp(t+1) into buffer pn ----
            float4 pre4;
            const bool do_pre = (rid < BPB * (D_ / 4)) && (t + 2 < T_);
            const int qq = rid >> 4, e = rid & 15;
            if (do_pre)
                pre4 = ((const float4*)(x + ((size_t)(b0 + qq) * T_ + (t + 2)) * D_))[e];
            if (t + 1 < T_) {
                BSYNCR(5 + pn, NTHR);                // wait: buffer pn free
                proj_step(sh_x[pn], sh_xp[pn]);      // xp(t+1)
                __threadfence_block();
                BARRR(3 + pn, NTHR);                 // RDY[pn]: xp(t+1) ready
            }
            if (do_pre)
                ((float4*)sh_x[pc][qq])[e] = pre4;   // stage x(t+2) into retired buffer
            BSYNC(7, GATE_T);                        // proj-internal ordering
        }
    }
    __syncthreads();

    // ---- publish h_T; elect last block ----
    if (is_gate && tid < G4)
        g_hT[(b0 + q0) * H_ + r] = h_;
    __threadfence();
    __syncthreads();
    if (tid == 0) {
        unsigned old = atomicAdd(&g_done, 1);
        s_last = (old == NBLK - 1) ? 1u : 0u;
    }
    __syncthreads();
    if (!s_last) return;
    if (tid == 0) g_done = 0;            // reset for deterministic graph replay
    __threadfence();

    // ---- BN stats (last block) ----
    if (tid < G4) {
        float s = 0.f, qs = 0.f;
        for (int b = q0 * (B_ / BPB); b < (q0 + 1) * (B_ / BPB); b++) {
            const float v = g_hT[b * H_ + r];
            s += v; qs += v * v;
        }
        sh_g[q0][r] = s;
        sh_h[q0 * 68 + r] = qs;
    }
    __syncthreads();
    if (tid < H_) {
        const float S = sh_g[0][tid] + sh_g[1][tid] + sh_g[2][tid] + sh_g[3][tid];
        const float Q = sh_h[0*68 + tid] + sh_h[1*68 + tid] + sh_h[2*68 + tid] + sh_h[3*68 + tid];
        const float mean = S * (1.f / B_);
        const float var  = Q * (1.f / B_) - mean * mean;
        const float a    = gamma[tid] * rsqrtf(var + 1e-5f);
        s_a[tid] = a * fc_w[tid];
        s_b[tid] = (beta[tid] - mean * a) * fc_w[tid];
    }
    __syncthreads();

    // ---- head ----
    const float f0 = fc_b[0];
    for (int b = tid; b < B_; b += NTHR) {
        float acc = f0;
        #pragma unroll
        for (int jj = 0; jj < H_; jj++)
            acc += s_a[jj] * g_hT[b * H_ + jj] + s_b[jj];
        out[b] = acc;
    }
}

extern "C" void kernel_launch(void* const* d_in, const int* in_sizes, int n_in,
                              void* d_out, int out_size)
{
    const float* x     = (const float*)d_in[0];
    const float* W_ih  = (const float*)d_in[1];
    const float* W_hh  = (const float*)d_in[2];
    const float* b_ih  = (const float*)d_in[3];
    const float* b_hh  = (const float*)d_in[4];
    const float* gamma = (const float*)d_in[5];
    const float* beta  = (const float*)d_in[6];
    const float* fc_w  = (const float*)d_in[7];
    const float* fc_b  = (const float*)d_in[8];
    float* out = (float*)d_out;

    fused_lstm_ws<<<NBLK, NTHR>>>(x, W_ih, W_hh, b_ih, b_hh,
                                  gamma, beta, fc_w, fc_b, out);
}